// round 2
// baseline (speedup 1.0000x reference)
#include <cuda_runtime.h>
#include <cuda_bf16.h>

#define N_NODES 100000
#define D 32

// Scratch (allocation-free rule: __device__ globals)
__device__ float g_agg[N_NODES * D];   // aggregation buffer (reused per layer)
__device__ float g_h1[N_NODES * D];    // layer-1 output
__device__ float g_deg[N_NODES];       // in-degree (float), computed once

// ---------------------------------------------------------------------------
__global__ void zero_kernel(float* __restrict__ p, int n) {
    int i = blockIdx.x * blockDim.x + threadIdx.x;
    int stride = gridDim.x * blockDim.x;
    for (; i < n; i += stride) p[i] = 0.0f;
}

// ---------------------------------------------------------------------------
// Edge scatter: 8 threads per edge, float4 per thread (32 floats/edge).
// Gathers x[src] row, atomic-adds into agg[dst] row. Optionally counts degree.
template <bool ADD_DEG>
__global__ void scatter_kernel(const float* __restrict__ x,
                               const int* __restrict__ src,
                               const int* __restrict__ dst,
                               float* __restrict__ agg,
                               int E) {
    int gid = blockIdx.x * blockDim.x + threadIdx.x;
    int e = gid >> 3;          // edge index
    int sub = gid & 7;         // float4 slot within the 32-float row
    if (e >= E) return;

    int s = src[e];
    int d = dst[e];

    const float4 v = *reinterpret_cast<const float4*>(x + (size_t)s * D + sub * 4);
    float* out = agg + (size_t)d * D + sub * 4;
    atomicAdd(out + 0, v.x);
    atomicAdd(out + 1, v.y);
    atomicAdd(out + 2, v.z);
    atomicAdd(out + 3, v.w);

    if (ADD_DEG && sub == 0) {
        atomicAdd(&g_deg[d], 1.0f);
    }
}

// ---------------------------------------------------------------------------
// Node transform: out[n] = relu( (agg[n]/max(deg,1)) @ Wl + b + root[n] @ Wr )
// One warp per node; lane c owns output column c. Inputs broadcast via shfl.
__global__ void transform_kernel(const float* __restrict__ agg,
                                 const float* __restrict__ root,
                                 const float* __restrict__ deg,
                                 const float* __restrict__ Wl,
                                 const float* __restrict__ Wr,
                                 const float* __restrict__ b,
                                 float* __restrict__ out) {
    __shared__ float sWl[D * D];
    __shared__ float sWr[D * D];
    __shared__ float sb[D];

    int tid = threadIdx.x;
    for (int i = tid; i < D * D; i += blockDim.x) {
        sWl[i] = Wl[i];
        sWr[i] = Wr[i];
    }
    if (tid < D) sb[tid] = b[tid];
    __syncthreads();

    int warp = tid >> 5;
    int lane = tid & 31;
    int n = blockIdx.x * (blockDim.x >> 5) + warp;
    if (n >= N_NODES) return;

    float a = agg[(size_t)n * D + lane];    // aggregated feature, column `lane`
    float r = root[(size_t)n * D + lane];   // root feature, column `lane`
    float dg = deg[n];
    float inv = 1.0f / fmaxf(dg, 1.0f);

    float accA = 0.0f;
    float accR = 0.0f;
#pragma unroll
    for (int k = 0; k < D; k++) {
        float ak = __shfl_sync(0xffffffffu, a, k);
        float rk = __shfl_sync(0xffffffffu, r, k);
        accA = fmaf(ak, sWl[k * D + lane], accA);
        accR = fmaf(rk, sWr[k * D + lane], accR);
    }
    float o = fmaf(accA, inv, sb[lane]) + accR;
    out[(size_t)n * D + lane] = fmaxf(o, 0.0f);
}

// ---------------------------------------------------------------------------
extern "C" void kernel_launch(void* const* d_in, const int* in_sizes, int n_in,
                              void* d_out, int out_size) {
    const float* x = (const float*)d_in[0];
    const int* edge_index = (const int*)d_in[1];   // int32 (JAX x64 disabled)
    const float* W1l = (const float*)d_in[2];
    const float* W1r = (const float*)d_in[3];
    const float* b1  = (const float*)d_in[4];
    const float* W2l = (const float*)d_in[5];
    const float* W2r = (const float*)d_in[6];
    const float* b2  = (const float*)d_in[7];
    float* out = (float*)d_out;

    const int E = in_sizes[1] / 2;
    const int* src = edge_index;
    const int* dst = edge_index + E;

    float* agg; cudaGetSymbolAddress((void**)&agg, g_agg);
    float* h1;  cudaGetSymbolAddress((void**)&h1, g_h1);
    float* deg; cudaGetSymbolAddress((void**)&deg, g_deg);

    const int TPB = 256;
    const int feat_elems = N_NODES * D;
    const int zero_blocks = (feat_elems + TPB - 1) / TPB;
    const int scat_blocks = (int)(((long long)E * 8 + TPB - 1) / TPB);
    const int xf_blocks = (N_NODES + 7) / 8;   // 8 warps per block

    // ---- Layer 1 ----
    zero_kernel<<<zero_blocks, TPB>>>(agg, feat_elems);
    zero_kernel<<<(N_NODES + TPB - 1) / TPB, TPB>>>(deg, N_NODES);
    scatter_kernel<true><<<scat_blocks, TPB>>>(x, src, dst, agg, E);
    transform_kernel<<<xf_blocks, TPB>>>(agg, x, deg, W1l, W1r, b1, h1);

    // ---- Layer 2 (degree unchanged) ----
    zero_kernel<<<zero_blocks, TPB>>>(agg, feat_elems);
    scatter_kernel<false><<<scat_blocks, TPB>>>(h1, src, dst, agg, E);
    transform_kernel<<<xf_blocks, TPB>>>(agg, h1, deg, W2l, W2r, b2, out);
}

// round 3
// speedup vs baseline: 1.6812x; 1.6812x over previous
#include <cuda_runtime.h>
#include <cuda_bf16.h>

#define N_NODES 100000
#define D 32
#define EMAX 2000000

// ------------------------- scratch (__device__ globals) --------------------
__device__ float g_agg[N_NODES * D];     // aggregated mean features
__device__ float g_h1[N_NODES * D];      // layer-1 output
__device__ int   g_deg[N_NODES];         // in-degree histogram
__device__ int   g_tmp[N_NODES];         // block-local exclusive prefix
__device__ int   g_bsums[128];           // per-block sums for scan
__device__ int   g_rowptr[N_NODES + 1];  // CSR row pointers
__device__ int   g_cnt[N_NODES];         // fill cursors
__device__ int   g_csr[EMAX];            // CSR column (src) indices

// ---------------------------------------------------------------------------
__global__ void zero_int_kernel(int* __restrict__ p, int n) {
    int i = blockIdx.x * blockDim.x + threadIdx.x;
    if (i < n) p[i] = 0;
}

// in-degree histogram over dst
__global__ void hist_kernel(const int* __restrict__ dst, int* __restrict__ deg, int E) {
    int e = blockIdx.x * blockDim.x + threadIdx.x;
    if (e < E) atomicAdd(&deg[dst[e]], 1);
}

// ---- exclusive scan of deg -> rowptr (3 phases, 1024 elems per block) ------
__global__ void scan1_kernel(const int* __restrict__ deg, int* __restrict__ tmp,
                             int* __restrict__ bsums, int n) {
    __shared__ int warpEx[8];
    int t = threadIdx.x;
    int lane = t & 31, wid = t >> 5;
    int base = blockIdx.x * 1024;
    int idx0 = base + t * 4;

    int pre[4];
    int s = 0;
#pragma unroll
    for (int i = 0; i < 4; i++) {
        int id = idx0 + i;
        int d = (id < n) ? deg[id] : 0;
        pre[i] = s;
        s += d;
    }
    // inclusive warp scan of thread sums
    int inc = s;
#pragma unroll
    for (int o = 1; o < 32; o <<= 1) {
        int u = __shfl_up_sync(0xffffffffu, inc, o);
        if (lane >= o) inc += u;
    }
    if (lane == 31) warpEx[wid] = inc;
    __syncthreads();
    if (t == 0) {
        int run = 0;
#pragma unroll
        for (int i = 0; i < 8; i++) { int v = warpEx[i]; warpEx[i] = run; run += v; }
        bsums[blockIdx.x] = run;
    }
    __syncthreads();
    int thrEx = warpEx[wid] + (inc - s);   // exclusive offset of this thread in block
#pragma unroll
    for (int i = 0; i < 4; i++) {
        int id = idx0 + i;
        if (id < n) tmp[id] = thrEx + pre[i];
    }
}

__global__ void scan2_kernel(int* __restrict__ bsums, int nb) {
    // single block; nb <= 128; trivial sequential exclusive scan by thread 0
    if (threadIdx.x == 0) {
        int run = 0;
        for (int i = 0; i < nb; i++) { int v = bsums[i]; bsums[i] = run; run += v; }
    }
}

__global__ void scan3_kernel(const int* __restrict__ tmp, const int* __restrict__ bsums,
                             int* __restrict__ rowptr, int* __restrict__ cnt,
                             int n, int E) {
    int i = blockIdx.x * blockDim.x + threadIdx.x;
    if (i < n) {
        rowptr[i] = tmp[i] + bsums[i >> 10];
        cnt[i] = 0;
    }
    if (i == 0) rowptr[n] = E;
}

// fill CSR edge array
__global__ void fill_kernel(const int* __restrict__ src, const int* __restrict__ dst,
                            const int* __restrict__ rowptr, int* __restrict__ cnt,
                            int* __restrict__ csr, int E) {
    int e = blockIdx.x * blockDim.x + threadIdx.x;
    if (e < E) {
        int d = dst[e];
        int p = rowptr[d] + atomicAdd(&cnt[d], 1);
        csr[p] = src[e];
    }
}

// ---------------------------------------------------------------------------
// Gather-mean: warp per node. lane = feature column. Coalesced 128B row loads.
__global__ void gather_kernel(const float* __restrict__ x,
                              const int* __restrict__ rowptr,
                              const int* __restrict__ csr,
                              float* __restrict__ agg, int n) {
    int gw = (blockIdx.x * blockDim.x + threadIdx.x) >> 5;
    int lane = threadIdx.x & 31;
    if (gw >= n) return;

    int beg = rowptr[gw];
    int end = rowptr[gw + 1];

    float acc0 = 0.0f, acc1 = 0.0f;
    for (int j = beg; j < end; j += 32) {
        int m = end - j;
        if (m > 32) m = 32;
        int s = (lane < m) ? csr[j + lane] : 0;
        int jj = 0;
        for (; jj + 1 < m; jj += 2) {
            int s0 = __shfl_sync(0xffffffffu, s, jj);
            int s1 = __shfl_sync(0xffffffffu, s, jj + 1);
            acc0 += x[(size_t)s0 * D + lane];
            acc1 += x[(size_t)s1 * D + lane];
        }
        if (jj < m) {
            int s0 = __shfl_sync(0xffffffffu, s, jj);
            acc0 += x[(size_t)s0 * D + lane];
        }
    }
    float degf = (float)(end - beg);
    float inv = 1.0f / fmaxf(degf, 1.0f);
    agg[(size_t)gw * D + lane] = (acc0 + acc1) * inv;
}

// ---------------------------------------------------------------------------
// Transform: out[n] = relu( agg[n] @ Wl + b + root[n] @ Wr )
// lane = output column; W columns held in registers; node inputs read as
// uniform-address float4 broadcasts. Grid-stride over nodes amortizes W load.
__global__ void transform_kernel(const float* __restrict__ agg,
                                 const float* __restrict__ root,
                                 const float* __restrict__ Wl,
                                 const float* __restrict__ Wr,
                                 const float* __restrict__ b,
                                 float* __restrict__ out, int n) {
    int lane = threadIdx.x & 31;
    int w = blockIdx.x * (blockDim.x >> 5) + (threadIdx.x >> 5);
    int nWarps = gridDim.x * (blockDim.x >> 5);

    float wl[D], wr[D];
#pragma unroll
    for (int k = 0; k < D; k++) {
        wl[k] = Wl[k * D + lane];
        wr[k] = Wr[k * D + lane];
    }
    float bias = b[lane];

    for (int node = w; node < n; node += nWarps) {
        const float4* ap = reinterpret_cast<const float4*>(agg + (size_t)node * D);
        const float4* rp = reinterpret_cast<const float4*>(root + (size_t)node * D);
        float accA = 0.0f, accR = 0.0f;
#pragma unroll
        for (int k0 = 0; k0 < D / 4; k0++) {
            float4 a = ap[k0];   // uniform address -> broadcast LDG.128
            float4 r = rp[k0];
            accA = fmaf(a.x, wl[4 * k0 + 0], accA);
            accA = fmaf(a.y, wl[4 * k0 + 1], accA);
            accA = fmaf(a.z, wl[4 * k0 + 2], accA);
            accA = fmaf(a.w, wl[4 * k0 + 3], accA);
            accR = fmaf(r.x, wr[4 * k0 + 0], accR);
            accR = fmaf(r.y, wr[4 * k0 + 1], accR);
            accR = fmaf(r.z, wr[4 * k0 + 2], accR);
            accR = fmaf(r.w, wr[4 * k0 + 3], accR);
        }
        float o = accA + bias + accR;
        out[(size_t)node * D + lane] = fmaxf(o, 0.0f);
    }
}

// ---------------------------------------------------------------------------
extern "C" void kernel_launch(void* const* d_in, const int* in_sizes, int n_in,
                              void* d_out, int out_size) {
    const float* x = (const float*)d_in[0];
    const int* edge_index = (const int*)d_in[1];   // int32 (JAX x64 disabled)
    const float* W1l = (const float*)d_in[2];
    const float* W1r = (const float*)d_in[3];
    const float* b1  = (const float*)d_in[4];
    const float* W2l = (const float*)d_in[5];
    const float* W2r = (const float*)d_in[6];
    const float* b2  = (const float*)d_in[7];
    float* out = (float*)d_out;

    const int E = in_sizes[1] / 2;
    const int N = N_NODES;
    const int* src = edge_index;
    const int* dst = edge_index + E;

    float* agg;   cudaGetSymbolAddress((void**)&agg, g_agg);
    float* h1;    cudaGetSymbolAddress((void**)&h1, g_h1);
    int* deg;     cudaGetSymbolAddress((void**)&deg, g_deg);
    int* tmp;     cudaGetSymbolAddress((void**)&tmp, g_tmp);
    int* bsums;   cudaGetSymbolAddress((void**)&bsums, g_bsums);
    int* rowptr;  cudaGetSymbolAddress((void**)&rowptr, g_rowptr);
    int* cnt;     cudaGetSymbolAddress((void**)&cnt, g_cnt);
    int* csr;     cudaGetSymbolAddress((void**)&csr, g_csr);

    const int TPB = 256;
    const int nb_nodes = (N + TPB - 1) / TPB;           // 391
    const int nb_edges = (E + TPB - 1) / TPB;           // 6250
    const int nb_scan = (N + 1023) / 1024;              // 98
    const int nb_gather = (N * 32 + TPB - 1) / TPB;     // 12500 (warp/node)
    const int nb_xform = 600;                           // grid-stride

    // ---- CSR build (reused by both layers) ----
    zero_int_kernel<<<nb_nodes, TPB>>>(deg, N);
    hist_kernel<<<nb_edges, TPB>>>(dst, deg, E);
    scan1_kernel<<<nb_scan, TPB>>>(deg, tmp, bsums, N);
    scan2_kernel<<<1, 32>>>(bsums, nb_scan);
    scan3_kernel<<<nb_nodes, TPB>>>(tmp, bsums, rowptr, cnt, N, E);
    fill_kernel<<<nb_edges, TPB>>>(src, dst, rowptr, cnt, csr, E);

    // ---- Layer 1 ----
    gather_kernel<<<nb_gather, TPB>>>(x, rowptr, csr, agg, N);
    transform_kernel<<<nb_xform, TPB>>>(agg, x, W1l, W1r, b1, h1, N);

    // ---- Layer 2 ----
    gather_kernel<<<nb_gather, TPB>>>(h1, rowptr, csr, agg, N);
    transform_kernel<<<nb_xform, TPB>>>(agg, h1, W2l, W2r, b2, out, N);
}